// round 12
// baseline (speedup 1.0000x reference)
#include <cuda_runtime.h>
#include <math.h>
#include <stdint.h>

// ---------------------------------------------------------------------------
// GNN-TCN: receptive-field truncation + f32x2 conv + fused GAT.
// R11: occupancy-quantization fix on conv stages 1/2/4 (TSPLIT=4, minb=2).
// B=64, N=40, W=256, Fin=64, H=4, D=32, C=128, L=4, K=3, FC=128, out=(64,7)
// ---------------------------------------------------------------------------

#define SEQ    2560         // B*N
#define WT     61           // truncated window
#define BUFSTR (WT * 128)   // floats per sequence per stage buffer

__device__ float g_bufA[SEQ * BUFSTR];
__device__ float g_bufB[SEQ * BUFSTR];
__device__ float g_bufC[SEQ * BUFSTR];
__device__ float2 g_wP[8 * 192 * 128];      // paired conv weights [st][(p*3+k)*128+co]
__device__ float2 g_pw[32 * 128];           // paired proj weights [fpair*128+c]
__device__ float g_al[8 * 128];             // fused BN scale
__device__ float g_be[8 * 128];             // fused BN shift (incl conv bias)

typedef unsigned long long ull;

__device__ __forceinline__ ull ffma2(ull a, ull b, ull c) {
    ull d;
    asm("fma.rn.f32x2 %0, %1, %2, %3;" : "=l"(d) : "l"(a), "l"(b), "l"(c));
    return d;
}
__device__ __forceinline__ ull pack2(float lo, float hi) {
    ull d;
    asm("mov.b64 %0, {%1, %2};" : "=l"(d) : "f"(lo), "f"(hi));
    return d;
}
__device__ __forceinline__ float hsum2(ull a) {
    float lo, hi;
    asm("mov.b64 {%0, %1}, %2;" : "=f"(lo), "=f"(hi) : "l"(a));
    return lo + hi;
}
__device__ __forceinline__ float gelu_f(float x) {
    return 0.5f * x * (1.0f + erff(x * 0.70710678118654752440f));
}
__device__ __forceinline__ float warp_max(float v) {
    #pragma unroll
    for (int o = 16; o > 0; o >>= 1) v = fmaxf(v, __shfl_xor_sync(0xffffffffu, v, o));
    return v;
}
__device__ __forceinline__ float warp_sum(float v) {
    #pragma unroll
    for (int o = 16; o > 0; o >>= 1) v += __shfl_xor_sync(0xffffffffu, v, o);
    return v;
}
__device__ __forceinline__ float* selbuf(int s) {
    return (s == 0) ? g_bufA : (s == 1) ? g_bufB : g_bufC;
}

// ---------------------------------------------------------------------------
// Prep: pair conv weights (ci pairs) and proj weights (f pairs); fold BN.
// ---------------------------------------------------------------------------
__global__ void prep_k(const float* __restrict__ c1w, const float* __restrict__ c1b,
                       const float* __restrict__ c2w, const float* __restrict__ c2b,
                       const float* __restrict__ bn1s, const float* __restrict__ bn1b,
                       const float* __restrict__ bn1m, const float* __restrict__ bn1v,
                       const float* __restrict__ bn2s, const float* __restrict__ bn2b,
                       const float* __restrict__ bn2m, const float* __restrict__ bn2v,
                       const float* __restrict__ gat_w) {
    int idx = blockIdx.x * blockDim.x + threadIdx.x;
    int stride = gridDim.x * blockDim.x;
    for (int i = idx; i < 8 * 192 * 128; i += stride) {
        int st = i / 24576;
        int r  = i % 24576;
        int co = r & 127;
        int q  = r >> 7;
        int k  = q % 3;
        int p  = q / 3;
        int l  = st >> 1;
        const float* src = (st & 1) ? c2w : c1w;
        float we = src[(((size_t)l * 128 + co) * 128 + (2 * p + 0)) * 3 + k];
        float wo = src[(((size_t)l * 128 + co) * 128 + (2 * p + 1)) * 3 + k];
        g_wP[i] = make_float2(we, wo);
    }
    for (int i = idx; i < 32 * 128; i += stride) {
        int p = i >> 7, c = i & 127;
        g_pw[i] = make_float2(gat_w[c * 64 + 2 * p], gat_w[c * 64 + 2 * p + 1]);
    }
    for (int i = idx; i < 8 * 128; i += stride) {
        int st = i >> 7, co = i & 127, l = st >> 1;
        const float *s_, *b_, *m_, *v_, *cb;
        if (st & 1) { s_ = bn2s; b_ = bn2b; m_ = bn2m; v_ = bn2v; cb = c2b; }
        else        { s_ = bn1s; b_ = bn1b; m_ = bn1m; v_ = bn1v; cb = c1b; }
        float al = s_[l * 128 + co] * rsqrtf(v_[l * 128 + co] + 1e-5f);
        g_al[i] = al;
        g_be[i] = (cb[l * 128 + co] - m_[l * 128 + co]) * al + b_[l * 128 + co];
    }
}

// ---------------------------------------------------------------------------
// Fused GAT: projection + attention + aggregation + LayerNorm.
// One block per (b, w), 256 threads = (c: 128) x (half: 2).
// xs (10KB) aliases attn (25.6KB): xs is dead before attn is written.
// ---------------------------------------------------------------------------
__global__ void __launch_bounds__(256) gat_fused_k(const float* __restrict__ x,
                                                   const float* __restrict__ adj,
                                                   const float* __restrict__ a_src,
                                                   const float* __restrict__ a_dst,
                                                   const float* __restrict__ ln_g,
                                                   const float* __restrict__ ln_b) {
    __shared__ __align__(16) float attn_xs[6400];    // 25600 B; xs = first 2560 floats
    __shared__ __align__(16) float hs[40 * 128];     // 20480 B (h, then gat)
    __shared__ ull adjmask[40];                      // 320 B
    __shared__ float es[160], ed[160];               // 1280 B
    __shared__ float as_s[128], ad_s[128];           // 1024 B  (total 48704 B)

    const int w = blockIdx.x, b = blockIdx.y;
    const int tid = threadIdx.x;
    float* xs = attn_xs;                             // [n*64 + f], 40 x 64

    // Load x slice for this (b, w): 40 rows of 64 floats (coalesced float4).
    for (int i = tid; i < 640; i += 256) {
        int n = i >> 4, f4 = i & 15;
        const float4* src = (const float4*)(x
            + (((size_t)(b * 40 + n)) * 256 + 195 + w) * 64);
        ((float4*)xs)[i] = src[f4];
    }
    if (tid < 40) {
        ull m = 0;
        for (int j = 0; j < 40; ++j)
            if (adj[tid * 40 + j] != 0.f) m |= (1ull << j);
        adjmask[tid] = m;
    }
    if (tid < 128) { as_s[tid] = a_src[tid]; ad_s[tid] = a_dst[tid]; }
    __syncthreads();

    // Projection: h[n][c] = x[n][:] . gat_w[c][:], f32x2 over f-pairs.
    const int c = tid & 127, half = tid >> 7;
    {
        ull acc[20];
        #pragma unroll
        for (int ln = 0; ln < 20; ++ln) acc[ln] = 0ull;
        const ull* __restrict__ pw = (const ull*)g_pw + c;
        for (int p = 0; p < 32; p += 2) {
            ull w0 = pw[(p + 0) * 128];
            ull w1 = pw[(p + 1) * 128];
            #pragma unroll
            for (int ln = 0; ln < 20; ++ln) {
                int n = half * 20 + ln;
                ulonglong2 sv = *(const ulonglong2*)(xs + n * 64 + 2 * p);
                acc[ln] = ffma2(w0, sv.x, acc[ln]);
                acc[ln] = ffma2(w1, sv.y, acc[ln]);
            }
        }
        #pragma unroll
        for (int ln = 0; ln < 20; ++ln)
            hs[(half * 20 + ln) * 128 + c] = hsum2(acc[ln]);
    }
    __syncthreads();   // h complete; xs fully consumed (attn alias now safe)

    // Scores e_src/e_dst per (n, head).
    for (int p = tid; p < 160; p += 256) {
        int n = p >> 2, hd = p & 3;
        const float* hr = hs + n * 128 + hd * 32;
        float s1 = 0.f, s2 = 0.f;
        #pragma unroll
        for (int d = 0; d < 32; ++d) {
            float hv = hr[d];
            s1 = fmaf(hv, as_s[hd * 32 + d], s1);
            s2 = fmaf(hv, ad_s[hd * 32 + d], s2);
        }
        es[p] = s1; ed[p] = s2;
    }
    __syncthreads();

    const int lane = tid & 31;
    const int warp = tid >> 5;
    const int headA = warp & 3;      // Phase A: warp handles this head
    const int segA  = warp >> 2;     // and this n-range (0..1)
    float* attn = attn_xs;

    // Phase A: softmax attention weights into smem.
    for (int n = segA * 20; n < segA * 20 + 20; ++n) {
        float esn = es[n * 4 + headA];
        ull m = adjmask[n];
        int j0 = lane, j1 = lane + 32;
        float sc0 = -1e9f, sc1 = -1e9f;
        if ((m >> j0) & 1) {
            float v = esn + ed[j0 * 4 + headA];
            sc0 = (v > 0.f) ? v : 0.2f * v;
        }
        if (j1 < 40 && ((m >> j1) & 1)) {
            float v = esn + ed[j1 * 4 + headA];
            sc1 = (v > 0.f) ? v : 0.2f * v;
        }
        float mx = warp_max(fmaxf(sc0, sc1));
        float p0 = expf(sc0 - mx);
        float p1 = (j1 < 40) ? expf(sc1 - mx) : 0.f;
        float inv = 1.0f / warp_sum(p0 + p1);
        attn[headA * 1600 + n * 40 + j0] = p0 * inv;
        if (j1 < 40) attn[headA * 1600 + n * 40 + j1] = p1 * inv;
    }

    // Cache this thread's h column (all 40 j) before gs overwrites hs.
    ull hp[20];
    {
        float hcol[40];
        #pragma unroll
        for (int j = 0; j < 40; ++j) hcol[j] = hs[j * 128 + c];
        #pragma unroll
        for (int jj = 0; jj < 20; ++jj) hp[jj] = pack2(hcol[2 * jj], hcol[2 * jj + 1]);
    }
    __syncthreads();   // attn complete everywhere; all hs reads done

    // Phase B: packed aggregation; thread (c, half) does its 20 n.
    const float* arow = attn + (c >> 5) * 1600;
    for (int n = half * 20; n < half * 20 + 20; ++n) {
        const ull* ap = (const ull*)(arow + n * 40);
        ull acc0 = 0ull, acc1 = 0ull;
        #pragma unroll
        for (int jj = 0; jj < 20; jj += 2) {
            acc0 = ffma2(ap[jj],     hp[jj],     acc0);
            acc1 = ffma2(ap[jj + 1], hp[jj + 1], acc1);
        }
        hs[n * 128 + c] = hsum2(acc0) + hsum2(acc1);
    }
    __syncthreads();

    // LayerNorm over C=128 (8 warps, n strided by 8), write seq buffer.
    for (int n = warp; n < 40; n += 8) {
        float v0 = hs[n * 128 + lane];
        float v1 = hs[n * 128 + 32 + lane];
        float v2 = hs[n * 128 + 64 + lane];
        float v3 = hs[n * 128 + 96 + lane];
        float s  = warp_sum(v0 + v1 + v2 + v3);
        float sq = warp_sum(v0 * v0 + v1 * v1 + v2 * v2 + v3 * v3);
        float mu = s * (1.0f / 128.0f);
        float var = sq * (1.0f / 128.0f) - mu * mu;
        float rstd = rsqrtf(var + 1e-5f);
        size_t base = ((size_t)(b * 40 + n)) * BUFSTR + (size_t)w * 128;
        g_bufA[base + lane]      = (v0 - mu) * rstd * ln_g[lane]      + ln_b[lane];
        g_bufA[base + 32 + lane] = (v1 - mu) * rstd * ln_g[32 + lane] + ln_b[32 + lane];
        g_bufA[base + 64 + lane] = (v2 - mu) * rstd * ln_g[64 + lane] + ln_b[64 + lane];
        g_bufA[base + 96 + lane] = (v3 - mu) * rstd * ln_g[96 + lane] + ln_b[96 + lane];
    }
}

// ---------------------------------------------------------------------------
// TCN conv stage: f32x2 packed over ci pairs, NS seqs/block, TSPLIT t-groups,
// MINB blocks/SM floor (reg forcing).
// ---------------------------------------------------------------------------
template <int OUTC, int A, bool RES, int NS, int TSPLIT, int MINB>
__global__ void __launch_bounds__(128 * TSPLIT, MINB)
conv_stage_k(int in_sel, int res_sel, int out_sel, int stage) {
    constexpr int INC  = A * (OUTC - 1) + 3;
    constexpr int OG   = (OUTC + TSPLIT - 1) / TSPLIT;
    constexpr int ING  = A * (OG - 1) + 3;
    constexpr int ROWS = A * (TSPLIT * OG - 1) + 3;
    __shared__ __align__(16) float s_in[NS * ROWS * 128];
    const int co  = threadIdx.x & 127;
    const int grp = threadIdx.x >> 7;
    const int t0  = grp * OG;

    #pragma unroll
    for (int q = 0; q < NS; ++q) {
        const float4* gin = (const float4*)(selbuf(in_sel)
                              + (size_t)(blockIdx.x * NS + q) * BUFSTR);
        float4* dst = (float4*)(s_in + q * ROWS * 128);
        for (int i = threadIdx.x; i < ROWS * 32; i += 128 * TSPLIT)
            dst[i] = (i < INC * 32) ? gin[i] : make_float4(0.f, 0.f, 0.f, 0.f);
    }
    __syncthreads();

    ull acc[NS][OG];
    #pragma unroll
    for (int q = 0; q < NS; ++q)
        #pragma unroll
        for (int t = 0; t < OG; ++t) acc[q][t] = 0ull;

    const ull* __restrict__ wp = (const ull*)g_wP + stage * 24576 + co;
    const int rowbase = A * t0;
    for (int g = 0; g < 32; ++g) {
        ull w0a = wp[((2 * g + 0) * 3 + 0) * 128];
        ull w1a = wp[((2 * g + 0) * 3 + 1) * 128];
        ull w2a = wp[((2 * g + 0) * 3 + 2) * 128];
        ull w0b = wp[((2 * g + 1) * 3 + 0) * 128];
        ull w1b = wp[((2 * g + 1) * 3 + 1) * 128];
        ull w2b = wp[((2 * g + 1) * 3 + 2) * 128];
        #pragma unroll
        for (int q = 0; q < NS; ++q) {
            const ulonglong2* srow =
                (const ulonglong2*)(s_in + (q * ROWS + rowbase) * 128) + g;
            #pragma unroll
            for (int r = 0; r < ING; ++r) {
                ulonglong2 sv = srow[r * 32];
                if (A == 1) {
                    if (r < OG) {
                        acc[q][r] = ffma2(w0a, sv.x, acc[q][r]);
                        acc[q][r] = ffma2(w0b, sv.y, acc[q][r]);
                    }
                    if (r >= 1 && r - 1 < OG) {
                        acc[q][r - 1] = ffma2(w1a, sv.x, acc[q][r - 1]);
                        acc[q][r - 1] = ffma2(w1b, sv.y, acc[q][r - 1]);
                    }
                    if (r >= 2) {
                        acc[q][r - 2] = ffma2(w2a, sv.x, acc[q][r - 2]);
                        acc[q][r - 2] = ffma2(w2b, sv.y, acc[q][r - 2]);
                    }
                } else {
                    if ((r & 1) == 0) {
                        if (r / 2 < OG) {
                            acc[q][r / 2] = ffma2(w0a, sv.x, acc[q][r / 2]);
                            acc[q][r / 2] = ffma2(w0b, sv.y, acc[q][r / 2]);
                        }
                        if (r >= 2) {
                            acc[q][(r - 2) / 2] = ffma2(w2a, sv.x, acc[q][(r - 2) / 2]);
                            acc[q][(r - 2) / 2] = ffma2(w2b, sv.y, acc[q][(r - 2) / 2]);
                        }
                    } else {
                        acc[q][(r - 1) / 2] = ffma2(w1a, sv.x, acc[q][(r - 1) / 2]);
                        acc[q][(r - 1) / 2] = ffma2(w1b, sv.y, acc[q][(r - 1) / 2]);
                    }
                }
            }
        }
    }

    const float al = g_al[stage * 128 + co];
    const float be = g_be[stage * 128 + co];
    #pragma unroll
    for (int q = 0; q < NS; ++q) {
        float* gout = selbuf(out_sel) + (size_t)(blockIdx.x * NS + q) * BUFSTR;
        const float* gres = selbuf(res_sel) + (size_t)(blockIdx.x * NS + q) * BUFSTR;
        #pragma unroll
        for (int lt = 0; lt < OG; ++lt) {
            int t = t0 + lt;
            if (TSPLIT == 1 || t < OUTC) {
                float v = gelu_f(fmaf(al, hsum2(acc[q][lt]), be));
                if (RES) v = gelu_f(v + gres[(4 + 2 * t) * 128 + co]);
                gout[t * 128 + co] = v;
            }
        }
    }
}

// ---------------------------------------------------------------------------
// Output head.
// ---------------------------------------------------------------------------
__global__ void __launch_bounds__(128) head_k(const float* __restrict__ f1w,
                                              const float* __restrict__ f1b,
                                              const float* __restrict__ f2w,
                                              const float* __restrict__ f2b,
                                              float* __restrict__ out) {
    __shared__ float hv[128];
    __shared__ float wsum[4];
    int blk = blockIdx.x;
    int b = blk / 7, n = blk % 7;
    int j = threadIdx.x;
    size_t s = (size_t)(b * 40 + n);
    hv[j] = g_bufA[s * BUFSTR + j];
    __syncthreads();
    float acc = f1b[j];
    const float* __restrict__ wr = f1w + (size_t)j * 128;
    #pragma unroll 8
    for (int c = 0; c < 128; ++c) acc = fmaf(__ldg(&wr[c]), hv[c], acc);
    float z = gelu_f(acc);
    float part = warp_sum(z * f2w[j]);
    if ((j & 31) == 0) wsum[j >> 5] = part;
    __syncthreads();
    if (j == 0) out[b * 7 + n] = wsum[0] + wsum[1] + wsum[2] + wsum[3] + f2b[0];
}

// ---------------------------------------------------------------------------
extern "C" void kernel_launch(void* const* d_in, const int* in_sizes, int n_in,
                              void* d_out, int out_size) {
    const float* x     = (const float*)d_in[0];
    const float* adj   = (const float*)d_in[1];
    const float* gat_w = (const float*)d_in[2];
    const float* a_src = (const float*)d_in[3];
    const float* a_dst = (const float*)d_in[4];
    const float* ln_g  = (const float*)d_in[5];
    const float* ln_b  = (const float*)d_in[6];
    const float* c1w   = (const float*)d_in[7];
    const float* c1b   = (const float*)d_in[8];
    const float* c2w   = (const float*)d_in[9];
    const float* c2b   = (const float*)d_in[10];
    const float* bn1s  = (const float*)d_in[11];
    const float* bn1b  = (const float*)d_in[12];
    const float* bn1m  = (const float*)d_in[13];
    const float* bn1v  = (const float*)d_in[14];
    const float* bn2s  = (const float*)d_in[15];
    const float* bn2b  = (const float*)d_in[16];
    const float* bn2m  = (const float*)d_in[17];
    const float* bn2v  = (const float*)d_in[18];
    const float* f1w   = (const float*)d_in[19];
    const float* f1b   = (const float*)d_in[20];
    const float* f2w   = (const float*)d_in[21];
    const float* f2b   = (const float*)d_in[22];
    float* out = (float*)d_out;

    prep_k<<<256, 256>>>(c1w, c1b, c2w, c2b, bn1s, bn1b, bn1m, bn1v,
                         bn2s, bn2b, bn2m, bn2v, gat_w);
    gat_fused_k<<<dim3(WT, 64), 256>>>(x, adj, a_src, a_dst, ln_g, ln_b);

    // TCN compact stages (R11: TSPLIT=4 + minb=2 on stages 0-2, 4)
    conv_stage_k<59, 1, false, 1, 4, 2><<<2560, 512>>>(0, 0, 1, 0); // seq->z0
    conv_stage_k<29, 2, true , 1, 4, 2><<<2560, 512>>>(1, 0, 2, 1); // z0+resA->cur1
    conv_stage_k<27, 1, false, 1, 4, 2><<<2560, 512>>>(2, 0, 1, 2); // cur1->z1
    conv_stage_k<13, 2, true , 1, 2, 3><<<2560, 256>>>(1, 2, 0, 3); // z1+resC->cur2
    conv_stage_k<11, 1, false, 2, 4, 2><<<1280, 512>>>(0, 0, 1, 4); // cur2->z2
    conv_stage_k< 5, 2, true , 4, 1, 1><<< 640, 128>>>(1, 0, 2, 5); // z2+resA->cur3
    conv_stage_k< 3, 1, false, 8, 1, 1><<< 320, 128>>>(2, 0, 1, 6); // cur3->z3
    conv_stage_k< 1, 2, true , 8, 1, 1><<< 320, 128>>>(1, 2, 0, 7); // z3+resC->cur4

    head_k<<<448, 128>>>(f1w, f1b, f2w, f2b, out);
}

// round 13
// speedup vs baseline: 1.0598x; 1.0598x over previous
#include <cuda_runtime.h>
#include <math.h>
#include <stdint.h>

// ---------------------------------------------------------------------------
// GNN-TCN: receptive-field truncation + f32x2 conv + fused GAT.
// R13: R10 launch config restored + weight prefetch (double-buffer) on the
// 3-block/SM conv stages (reg headroom verified).
// B=64, N=40, W=256, Fin=64, H=4, D=32, C=128, L=4, K=3, FC=128, out=(64,7)
// ---------------------------------------------------------------------------

#define SEQ    2560         // B*N
#define WT     61           // truncated window
#define BUFSTR (WT * 128)   // floats per sequence per stage buffer

__device__ float g_bufA[SEQ * BUFSTR];
__device__ float g_bufB[SEQ * BUFSTR];
__device__ float g_bufC[SEQ * BUFSTR];
__device__ float2 g_wP[8 * 192 * 128];      // paired conv weights [st][(p*3+k)*128+co]
__device__ float2 g_pw[32 * 128];           // paired proj weights [fpair*128+c]
__device__ float g_al[8 * 128];             // fused BN scale
__device__ float g_be[8 * 128];             // fused BN shift (incl conv bias)

typedef unsigned long long ull;

__device__ __forceinline__ ull ffma2(ull a, ull b, ull c) {
    ull d;
    asm("fma.rn.f32x2 %0, %1, %2, %3;" : "=l"(d) : "l"(a), "l"(b), "l"(c));
    return d;
}
__device__ __forceinline__ ull pack2(float lo, float hi) {
    ull d;
    asm("mov.b64 %0, {%1, %2};" : "=l"(d) : "f"(lo), "f"(hi));
    return d;
}
__device__ __forceinline__ float hsum2(ull a) {
    float lo, hi;
    asm("mov.b64 {%0, %1}, %2;" : "=f"(lo), "=f"(hi) : "l"(a));
    return lo + hi;
}
__device__ __forceinline__ float gelu_f(float x) {
    return 0.5f * x * (1.0f + erff(x * 0.70710678118654752440f));
}
__device__ __forceinline__ float warp_max(float v) {
    #pragma unroll
    for (int o = 16; o > 0; o >>= 1) v = fmaxf(v, __shfl_xor_sync(0xffffffffu, v, o));
    return v;
}
__device__ __forceinline__ float warp_sum(float v) {
    #pragma unroll
    for (int o = 16; o > 0; o >>= 1) v += __shfl_xor_sync(0xffffffffu, v, o);
    return v;
}
__device__ __forceinline__ float* selbuf(int s) {
    return (s == 0) ? g_bufA : (s == 1) ? g_bufB : g_bufC;
}

// ---------------------------------------------------------------------------
// Prep: pair conv weights (ci pairs) and proj weights (f pairs); fold BN.
// ---------------------------------------------------------------------------
__global__ void prep_k(const float* __restrict__ c1w, const float* __restrict__ c1b,
                       const float* __restrict__ c2w, const float* __restrict__ c2b,
                       const float* __restrict__ bn1s, const float* __restrict__ bn1b,
                       const float* __restrict__ bn1m, const float* __restrict__ bn1v,
                       const float* __restrict__ bn2s, const float* __restrict__ bn2b,
                       const float* __restrict__ bn2m, const float* __restrict__ bn2v,
                       const float* __restrict__ gat_w) {
    int idx = blockIdx.x * blockDim.x + threadIdx.x;
    int stride = gridDim.x * blockDim.x;
    for (int i = idx; i < 8 * 192 * 128; i += stride) {
        int st = i / 24576;
        int r  = i % 24576;
        int co = r & 127;
        int q  = r >> 7;
        int k  = q % 3;
        int p  = q / 3;
        int l  = st >> 1;
        const float* src = (st & 1) ? c2w : c1w;
        float we = src[(((size_t)l * 128 + co) * 128 + (2 * p + 0)) * 3 + k];
        float wo = src[(((size_t)l * 128 + co) * 128 + (2 * p + 1)) * 3 + k];
        g_wP[i] = make_float2(we, wo);
    }
    for (int i = idx; i < 32 * 128; i += stride) {
        int p = i >> 7, c = i & 127;
        g_pw[i] = make_float2(gat_w[c * 64 + 2 * p], gat_w[c * 64 + 2 * p + 1]);
    }
    for (int i = idx; i < 8 * 128; i += stride) {
        int st = i >> 7, co = i & 127, l = st >> 1;
        const float *s_, *b_, *m_, *v_, *cb;
        if (st & 1) { s_ = bn2s; b_ = bn2b; m_ = bn2m; v_ = bn2v; cb = c2b; }
        else        { s_ = bn1s; b_ = bn1b; m_ = bn1m; v_ = bn1v; cb = c1b; }
        float al = s_[l * 128 + co] * rsqrtf(v_[l * 128 + co] + 1e-5f);
        g_al[i] = al;
        g_be[i] = (cb[l * 128 + co] - m_[l * 128 + co]) * al + b_[l * 128 + co];
    }
}

// ---------------------------------------------------------------------------
// Fused GAT: projection + attention + aggregation + LayerNorm.
// One block per (b, w), 256 threads = (c: 128) x (half: 2).
// xs (10KB) aliases attn (25.6KB): xs is dead before attn is written.
// ---------------------------------------------------------------------------
__global__ void __launch_bounds__(256) gat_fused_k(const float* __restrict__ x,
                                                   const float* __restrict__ adj,
                                                   const float* __restrict__ a_src,
                                                   const float* __restrict__ a_dst,
                                                   const float* __restrict__ ln_g,
                                                   const float* __restrict__ ln_b) {
    __shared__ __align__(16) float attn_xs[6400];    // 25600 B; xs = first 2560 floats
    __shared__ __align__(16) float hs[40 * 128];     // 20480 B (h, then gat)
    __shared__ ull adjmask[40];                      // 320 B
    __shared__ float es[160], ed[160];               // 1280 B
    __shared__ float as_s[128], ad_s[128];           // 1024 B  (total 48704 B)

    const int w = blockIdx.x, b = blockIdx.y;
    const int tid = threadIdx.x;
    float* xs = attn_xs;                             // [n*64 + f], 40 x 64

    for (int i = tid; i < 640; i += 256) {
        int n = i >> 4, f4 = i & 15;
        const float4* src = (const float4*)(x
            + (((size_t)(b * 40 + n)) * 256 + 195 + w) * 64);
        ((float4*)xs)[i] = src[f4];
    }
    if (tid < 40) {
        ull m = 0;
        for (int j = 0; j < 40; ++j)
            if (adj[tid * 40 + j] != 0.f) m |= (1ull << j);
        adjmask[tid] = m;
    }
    if (tid < 128) { as_s[tid] = a_src[tid]; ad_s[tid] = a_dst[tid]; }
    __syncthreads();

    // Projection: h[n][c] = x[n][:] . gat_w[c][:], f32x2 over f-pairs.
    const int c = tid & 127, half = tid >> 7;
    {
        ull acc[20];
        #pragma unroll
        for (int ln = 0; ln < 20; ++ln) acc[ln] = 0ull;
        const ull* __restrict__ pw = (const ull*)g_pw + c;
        for (int p = 0; p < 32; p += 2) {
            ull w0 = pw[(p + 0) * 128];
            ull w1 = pw[(p + 1) * 128];
            #pragma unroll
            for (int ln = 0; ln < 20; ++ln) {
                int n = half * 20 + ln;
                ulonglong2 sv = *(const ulonglong2*)(xs + n * 64 + 2 * p);
                acc[ln] = ffma2(w0, sv.x, acc[ln]);
                acc[ln] = ffma2(w1, sv.y, acc[ln]);
            }
        }
        #pragma unroll
        for (int ln = 0; ln < 20; ++ln)
            hs[(half * 20 + ln) * 128 + c] = hsum2(acc[ln]);
    }
    __syncthreads();   // h complete; xs fully consumed (attn alias now safe)

    // Scores e_src/e_dst per (n, head).
    for (int p = tid; p < 160; p += 256) {
        int n = p >> 2, hd = p & 3;
        const float* hr = hs + n * 128 + hd * 32;
        float s1 = 0.f, s2 = 0.f;
        #pragma unroll
        for (int d = 0; d < 32; ++d) {
            float hv = hr[d];
            s1 = fmaf(hv, as_s[hd * 32 + d], s1);
            s2 = fmaf(hv, ad_s[hd * 32 + d], s2);
        }
        es[p] = s1; ed[p] = s2;
    }
    __syncthreads();

    const int lane = tid & 31;
    const int warp = tid >> 5;
    const int headA = warp & 3;
    const int segA  = warp >> 2;
    float* attn = attn_xs;

    // Phase A: softmax attention weights into smem.
    for (int n = segA * 20; n < segA * 20 + 20; ++n) {
        float esn = es[n * 4 + headA];
        ull m = adjmask[n];
        int j0 = lane, j1 = lane + 32;
        float sc0 = -1e9f, sc1 = -1e9f;
        if ((m >> j0) & 1) {
            float v = esn + ed[j0 * 4 + headA];
            sc0 = (v > 0.f) ? v : 0.2f * v;
        }
        if (j1 < 40 && ((m >> j1) & 1)) {
            float v = esn + ed[j1 * 4 + headA];
            sc1 = (v > 0.f) ? v : 0.2f * v;
        }
        float mx = warp_max(fmaxf(sc0, sc1));
        float p0 = expf(sc0 - mx);
        float p1 = (j1 < 40) ? expf(sc1 - mx) : 0.f;
        float inv = 1.0f / warp_sum(p0 + p1);
        attn[headA * 1600 + n * 40 + j0] = p0 * inv;
        if (j1 < 40) attn[headA * 1600 + n * 40 + j1] = p1 * inv;
    }

    // Cache this thread's h column before gs overwrites hs.
    ull hp[20];
    {
        float hcol[40];
        #pragma unroll
        for (int j = 0; j < 40; ++j) hcol[j] = hs[j * 128 + c];
        #pragma unroll
        for (int jj = 0; jj < 20; ++jj) hp[jj] = pack2(hcol[2 * jj], hcol[2 * jj + 1]);
    }
    __syncthreads();

    // Phase B: packed aggregation; thread (c, half) does its 20 n.
    const float* arow = attn + (c >> 5) * 1600;
    for (int n = half * 20; n < half * 20 + 20; ++n) {
        const ull* ap = (const ull*)(arow + n * 40);
        ull acc0 = 0ull, acc1 = 0ull;
        #pragma unroll
        for (int jj = 0; jj < 20; jj += 2) {
            acc0 = ffma2(ap[jj],     hp[jj],     acc0);
            acc1 = ffma2(ap[jj + 1], hp[jj + 1], acc1);
        }
        hs[n * 128 + c] = hsum2(acc0) + hsum2(acc1);
    }
    __syncthreads();

    // LayerNorm over C=128, write seq buffer.
    for (int n = warp; n < 40; n += 8) {
        float v0 = hs[n * 128 + lane];
        float v1 = hs[n * 128 + 32 + lane];
        float v2 = hs[n * 128 + 64 + lane];
        float v3 = hs[n * 128 + 96 + lane];
        float s  = warp_sum(v0 + v1 + v2 + v3);
        float sq = warp_sum(v0 * v0 + v1 * v1 + v2 * v2 + v3 * v3);
        float mu = s * (1.0f / 128.0f);
        float var = sq * (1.0f / 128.0f) - mu * mu;
        float rstd = rsqrtf(var + 1e-5f);
        size_t base = ((size_t)(b * 40 + n)) * BUFSTR + (size_t)w * 128;
        g_bufA[base + lane]      = (v0 - mu) * rstd * ln_g[lane]      + ln_b[lane];
        g_bufA[base + 32 + lane] = (v1 - mu) * rstd * ln_g[32 + lane] + ln_b[32 + lane];
        g_bufA[base + 64 + lane] = (v2 - mu) * rstd * ln_g[64 + lane] + ln_b[64 + lane];
        g_bufA[base + 96 + lane] = (v3 - mu) * rstd * ln_g[96 + lane] + ln_b[96 + lane];
    }
}

// ---------------------------------------------------------------------------
// TCN conv stage: f32x2 packed over ci pairs, NS seqs/block, TSPLIT t-groups,
// optional weight double-buffering (PREF), MINB blocks/SM.
// ---------------------------------------------------------------------------
template <int OUTC, int A, bool RES, int NS, int TSPLIT, int MINB, bool PREF>
__global__ void __launch_bounds__(128 * TSPLIT, MINB)
conv_stage_k(int in_sel, int res_sel, int out_sel, int stage) {
    constexpr int INC  = A * (OUTC - 1) + 3;
    constexpr int OG   = (OUTC + TSPLIT - 1) / TSPLIT;
    constexpr int ING  = A * (OG - 1) + 3;
    constexpr int ROWS = A * (TSPLIT * OG - 1) + 3;
    __shared__ __align__(16) float s_in[NS * ROWS * 128];
    const int co  = threadIdx.x & 127;
    const int grp = threadIdx.x >> 7;
    const int t0  = grp * OG;

    #pragma unroll
    for (int q = 0; q < NS; ++q) {
        const float4* gin = (const float4*)(selbuf(in_sel)
                              + (size_t)(blockIdx.x * NS + q) * BUFSTR);
        float4* dst = (float4*)(s_in + q * ROWS * 128);
        for (int i = threadIdx.x; i < ROWS * 32; i += 128 * TSPLIT)
            dst[i] = (i < INC * 32) ? gin[i] : make_float4(0.f, 0.f, 0.f, 0.f);
    }
    __syncthreads();

    ull acc[NS][OG];
    #pragma unroll
    for (int q = 0; q < NS; ++q)
        #pragma unroll
        for (int t = 0; t < OG; ++t) acc[q][t] = 0ull;

    const ull* __restrict__ wp = (const ull*)g_wP + stage * 24576 + co;
    const int rowbase = A * t0;

    ull cw0a, cw1a, cw2a, cw0b, cw1b, cw2b;
    if (PREF) {
        cw0a = wp[0 * 128]; cw1a = wp[1 * 128]; cw2a = wp[2 * 128];
        cw0b = wp[3 * 128]; cw1b = wp[4 * 128]; cw2b = wp[5 * 128];
    }

    for (int g = 0; g < 32; ++g) {
        ull w0a, w1a, w2a, w0b, w1b, w2b;
        if (PREF) {
            w0a = cw0a; w1a = cw1a; w2a = cw2a;
            w0b = cw0b; w1b = cw1b; w2b = cw2b;
            int gn = (g < 31) ? g + 1 : 31;   // clamp: last iter reloads g=31
            cw0a = wp[((2 * gn + 0) * 3 + 0) * 128];
            cw1a = wp[((2 * gn + 0) * 3 + 1) * 128];
            cw2a = wp[((2 * gn + 0) * 3 + 2) * 128];
            cw0b = wp[((2 * gn + 1) * 3 + 0) * 128];
            cw1b = wp[((2 * gn + 1) * 3 + 1) * 128];
            cw2b = wp[((2 * gn + 1) * 3 + 2) * 128];
        } else {
            w0a = wp[((2 * g + 0) * 3 + 0) * 128];
            w1a = wp[((2 * g + 0) * 3 + 1) * 128];
            w2a = wp[((2 * g + 0) * 3 + 2) * 128];
            w0b = wp[((2 * g + 1) * 3 + 0) * 128];
            w1b = wp[((2 * g + 1) * 3 + 1) * 128];
            w2b = wp[((2 * g + 1) * 3 + 2) * 128];
        }
        #pragma unroll
        for (int q = 0; q < NS; ++q) {
            const ulonglong2* srow =
                (const ulonglong2*)(s_in + (q * ROWS + rowbase) * 128) + g;
            #pragma unroll
            for (int r = 0; r < ING; ++r) {
                ulonglong2 sv = srow[r * 32];
                if (A == 1) {
                    if (r < OG) {
                        acc[q][r] = ffma2(w0a, sv.x, acc[q][r]);
                        acc[q][r] = ffma2(w0b, sv.y, acc[q][r]);
                    }
                    if (r >= 1 && r - 1 < OG) {
                        acc[q][r - 1] = ffma2(w1a, sv.x, acc[q][r - 1]);
                        acc[q][r - 1] = ffma2(w1b, sv.y, acc[q][r - 1]);
                    }
                    if (r >= 2) {
                        acc[q][r - 2] = ffma2(w2a, sv.x, acc[q][r - 2]);
                        acc[q][r - 2] = ffma2(w2b, sv.y, acc[q][r - 2]);
                    }
                } else {
                    if ((r & 1) == 0) {
                        if (r / 2 < OG) {
                            acc[q][r / 2] = ffma2(w0a, sv.x, acc[q][r / 2]);
                            acc[q][r / 2] = ffma2(w0b, sv.y, acc[q][r / 2]);
                        }
                        if (r >= 2) {
                            acc[q][(r - 2) / 2] = ffma2(w2a, sv.x, acc[q][(r - 2) / 2]);
                            acc[q][(r - 2) / 2] = ffma2(w2b, sv.y, acc[q][(r - 2) / 2]);
                        }
                    } else {
                        acc[q][(r - 1) / 2] = ffma2(w1a, sv.x, acc[q][(r - 1) / 2]);
                        acc[q][(r - 1) / 2] = ffma2(w1b, sv.y, acc[q][(r - 1) / 2]);
                    }
                }
            }
        }
    }

    const float al = g_al[stage * 128 + co];
    const float be = g_be[stage * 128 + co];
    #pragma unroll
    for (int q = 0; q < NS; ++q) {
        float* gout = selbuf(out_sel) + (size_t)(blockIdx.x * NS + q) * BUFSTR;
        const float* gres = selbuf(res_sel) + (size_t)(blockIdx.x * NS + q) * BUFSTR;
        #pragma unroll
        for (int lt = 0; lt < OG; ++lt) {
            int t = t0 + lt;
            if (TSPLIT == 1 || t < OUTC) {
                float v = gelu_f(fmaf(al, hsum2(acc[q][lt]), be));
                if (RES) v = gelu_f(v + gres[(4 + 2 * t) * 128 + co]);
                gout[t * 128 + co] = v;
            }
        }
    }
}

// ---------------------------------------------------------------------------
// Output head.
// ---------------------------------------------------------------------------
__global__ void __launch_bounds__(128) head_k(const float* __restrict__ f1w,
                                              const float* __restrict__ f1b,
                                              const float* __restrict__ f2w,
                                              const float* __restrict__ f2b,
                                              float* __restrict__ out) {
    __shared__ float hv[128];
    __shared__ float wsum[4];
    int blk = blockIdx.x;
    int b = blk / 7, n = blk % 7;
    int j = threadIdx.x;
    size_t s = (size_t)(b * 40 + n);
    hv[j] = g_bufA[s * BUFSTR + j];
    __syncthreads();
    float acc = f1b[j];
    const float* __restrict__ wr = f1w + (size_t)j * 128;
    #pragma unroll 8
    for (int c = 0; c < 128; ++c) acc = fmaf(__ldg(&wr[c]), hv[c], acc);
    float z = gelu_f(acc);
    float part = warp_sum(z * f2w[j]);
    if ((j & 31) == 0) wsum[j >> 5] = part;
    __syncthreads();
    if (j == 0) out[b * 7 + n] = wsum[0] + wsum[1] + wsum[2] + wsum[3] + f2b[0];
}

// ---------------------------------------------------------------------------
extern "C" void kernel_launch(void* const* d_in, const int* in_sizes, int n_in,
                              void* d_out, int out_size) {
    const float* x     = (const float*)d_in[0];
    const float* adj   = (const float*)d_in[1];
    const float* gat_w = (const float*)d_in[2];
    const float* a_src = (const float*)d_in[3];
    const float* a_dst = (const float*)d_in[4];
    const float* ln_g  = (const float*)d_in[5];
    const float* ln_b  = (const float*)d_in[6];
    const float* c1w   = (const float*)d_in[7];
    const float* c1b   = (const float*)d_in[8];
    const float* c2w   = (const float*)d_in[9];
    const float* c2b   = (const float*)d_in[10];
    const float* bn1s  = (const float*)d_in[11];
    const float* bn1b  = (const float*)d_in[12];
    const float* bn1m  = (const float*)d_in[13];
    const float* bn1v  = (const float*)d_in[14];
    const float* bn2s  = (const float*)d_in[15];
    const float* bn2b  = (const float*)d_in[16];
    const float* bn2m  = (const float*)d_in[17];
    const float* bn2v  = (const float*)d_in[18];
    const float* f1w   = (const float*)d_in[19];
    const float* f1b   = (const float*)d_in[20];
    const float* f2w   = (const float*)d_in[21];
    const float* f2b   = (const float*)d_in[22];
    float* out = (float*)d_out;

    prep_k<<<256, 256>>>(c1w, c1b, c2w, c2b, bn1s, bn1b, bn1m, bn1v,
                         bn2s, bn2b, bn2m, bn2v, gat_w);
    gat_fused_k<<<dim3(WT, 64), 256>>>(x, adj, a_src, a_dst, ln_g, ln_b);

    // TCN stages: R10-proven shapes; PREF on the 3-block/SM (256-thread) stages.
    conv_stage_k<59, 1, false, 1, 4, 2, false><<<2560, 512>>>(0, 0, 1, 0); // seq->z0
    conv_stage_k<29, 2, true , 1, 2, 3, true ><<<2560, 256>>>(1, 0, 2, 1); // z0+resA->cur1
    conv_stage_k<27, 1, false, 1, 2, 3, true ><<<2560, 256>>>(2, 0, 1, 2); // cur1->z1
    conv_stage_k<13, 2, true , 1, 2, 3, true ><<<2560, 256>>>(1, 2, 0, 3); // z1+resC->cur2
    conv_stage_k<11, 1, false, 2, 2, 3, true ><<<1280, 256>>>(0, 0, 1, 4); // cur2->z2
    conv_stage_k< 5, 2, true , 4, 1, 1, false><<< 640, 128>>>(1, 0, 2, 5); // z2+resA->cur3
    conv_stage_k< 3, 1, false, 8, 1, 1, false><<< 320, 128>>>(2, 0, 1, 6); // cur3->z3
    conv_stage_k< 1, 2, true , 8, 1, 1, false><<< 320, 128>>>(1, 2, 0, 7); // z3+resC->cur4

    head_k<<<448, 128>>>(f1w, f1b, f2w, f2b, out);
}